// round 1
// baseline (speedup 1.0000x reference)
#include <cuda_runtime.h>
#include <stdint.h>

// Problem constants
#define BB 16
#define NN 25200
#define CC 80
#define MAXDET 100
#define KMAX 25              // ceil(NN / 1024)

// Output layout (flattened concat of reference outputs, float32):
//   boxes  [16][100][4] @ 0       (6400)
//   scores [16][100]    @ 6400    (1600)
//   classes[16][100][80]@ 8000    (128000)
//   counts [16]         @ 136000  (16)
#define OFF_BOX   0
#define OFF_SCORE 6400
#define OFF_CLS   8000
#define OFF_CNT   136000

// ---------------- scratch (__device__ globals: allowed, no allocs) ----------
__device__ float4 g_corners[BB][NN];     // compacted corners (x0,y0,x1,y1)
__device__ float  g_score[BB][NN];       // compacted scores (objectness)
__device__ int    g_idx[BB][NN];         // compacted -> original index
__device__ int    g_count[BB];           // compacted count per batch
__device__ float4 g_selbox[BB][MAXDET];
__device__ float  g_selscore[BB][MAXDET];
__device__ int    g_selidx[BB][MAXDET];
__device__ int    g_selcount[BB];

// ---------------------------------------------------------------------------
// Kernel 1: stable (index-ordered) compaction of boxes with score >= 0.5.
// One CTA per batch, sequential 1024-wide chunks with ballot prefix scan.
// Stable order => compacted slot order == original index order (tie-breaks).
// ---------------------------------------------------------------------------
__global__ void __launch_bounds__(1024, 1)
compact_kernel(const float* __restrict__ boxes, const float* __restrict__ obj)
{
    const int b   = blockIdx.x;
    const int tid = threadIdx.x;
    const int wid = tid >> 5;
    const int lane = tid & 31;

    __shared__ int warp_cnt[32];
    __shared__ int s_base;
    if (tid == 0) s_base = 0;
    __syncthreads();

    const float4* bx4 = reinterpret_cast<const float4*>(boxes);

    for (int start = 0; start < NN; start += 1024) {
        int n = start + tid;
        bool p = false;
        float sc = 0.0f;
        if (n < NN) {
            sc = obj[(size_t)b * NN + n];
            p = (sc >= 0.5f);
        }
        unsigned ball = __ballot_sync(0xffffffffu, p);
        int prefix = __popc(ball & ((1u << lane) - 1u));
        if (lane == 0) warp_cnt[wid] = __popc(ball);
        __syncthreads();

        int sum = 0, woff = 0;
        #pragma unroll
        for (int w = 0; w < 32; w++) {
            if (w == wid) woff = sum;
            sum += warp_cnt[w];
        }

        if (p) {
            int pos = s_base + woff + prefix;
            float4 v = bx4[(size_t)b * NN + n];   // (x, y, w, h)
            float hx = 0.5f * v.z;
            float hy = 0.5f * v.w;
            g_corners[b][pos] = make_float4(v.x - hx, v.y - hy, v.x + hx, v.y + hy);
            g_score[b][pos]   = sc;
            g_idx[b][pos]     = n;
        }
        __syncthreads();
        if (tid == 0) s_base += sum;
        // next chunk's first __syncthreads orders this update before reads
    }
    __syncthreads();
    if (tid == 0) g_count[b] = s_base;
}

// ---------------------------------------------------------------------------
// Kernel 2: greedy NMS. One CTA per batch, 1024 threads.
// Per round: fused (suppress vs previous winner) + (local argmax) in one pass
// over this thread's <=25 strided slots, then two-stage block argmax.
// Tie-break: higher score wins; equal score -> lower slot (== lower orig idx).
// ---------------------------------------------------------------------------
__global__ void __launch_bounds__(1024, 1)
nms_kernel()
{
    const int b   = blockIdx.x;
    const int tid = threadIdx.x;
    const int wid = tid >> 5;
    const int lane = tid & 31;

    const int cnt = g_count[b];
    const float4* __restrict__ cor = g_corners[b];

    // scores resident in registers; active bitmask in one register
    float sc[KMAX];
    unsigned mask = 0u;
    #pragma unroll
    for (int k = 0; k < KMAX; k++) {
        int slot = tid + (k << 10);
        if (slot < cnt) {
            sc[k] = g_score[b][slot];
            mask |= (1u << k);
        } else {
            sc[k] = -1.0f;
        }
    }

    __shared__ float  s_rs[32];
    __shared__ int    s_rslot[32];
    __shared__ float4 s_rc[32];
    __shared__ float  s_bs;
    __shared__ int    s_bslot;
    __shared__ float4 s_bc;

    float bx0 = 0.f, by0 = 0.f, bx1 = 0.f, by1 = 0.f, barea = 0.f;
    bool haveBest = false;
    int ndet = 0;

    for (int it = 0; it < MAXDET; it++) {
        float  lbs = -1.0f;
        int    lbslot = 0x7fffffff;
        float4 lbc = make_float4(0.f, 0.f, 0.f, 0.f);

        #pragma unroll
        for (int k = 0; k < KMAX; k++) {
            if ((mask >> k) & 1u) {
                int slot = tid + (k << 10);
                float4 c = cor[slot];
                if (haveBest) {
                    float ltx = fmaxf(bx0, c.x);
                    float lty = fmaxf(by0, c.y);
                    float rbx = fminf(bx1, c.z);
                    float rby = fminf(by1, c.w);
                    float w = fmaxf(rbx - ltx, 0.0f);
                    float h = fmaxf(rby - lty, 0.0f);
                    float inter = w * h;
                    float a2 = (c.z - c.x) * (c.w - c.y);
                    float denom = barea + a2 - inter + 1e-9f;
                    if (inter > 0.5f * denom) {     // iou > 0.5 -> suppress
                        mask &= ~(1u << k);
                        continue;
                    }
                }
                // '>' keeps lowest k on within-thread ties (slots ascending in k)
                if (sc[k] > lbs) {
                    lbs = sc[k];
                    lbslot = slot;
                    lbc = c;
                }
            }
        }

        // warp argmax reduce (score, then lower slot), carrying corners
        #pragma unroll
        for (int off = 16; off; off >>= 1) {
            float os   = __shfl_down_sync(0xffffffffu, lbs, off);
            int   osl  = __shfl_down_sync(0xffffffffu, lbslot, off);
            float ox   = __shfl_down_sync(0xffffffffu, lbc.x, off);
            float oy   = __shfl_down_sync(0xffffffffu, lbc.y, off);
            float oz   = __shfl_down_sync(0xffffffffu, lbc.z, off);
            float ow   = __shfl_down_sync(0xffffffffu, lbc.w, off);
            if (os > lbs || (os == lbs && osl < lbslot)) {
                lbs = os; lbslot = osl;
                lbc.x = ox; lbc.y = oy; lbc.z = oz; lbc.w = ow;
            }
        }
        if (lane == 0) {
            s_rs[wid] = lbs;
            s_rslot[wid] = lbslot;
            s_rc[wid] = lbc;
        }
        __syncthreads();

        if (wid == 0) {
            float  rs = s_rs[lane];
            int    rsl = s_rslot[lane];
            float4 rc = s_rc[lane];
            #pragma unroll
            for (int off = 16; off; off >>= 1) {
                float os  = __shfl_down_sync(0xffffffffu, rs, off);
                int   osl = __shfl_down_sync(0xffffffffu, rsl, off);
                float ox  = __shfl_down_sync(0xffffffffu, rc.x, off);
                float oy  = __shfl_down_sync(0xffffffffu, rc.y, off);
                float oz  = __shfl_down_sync(0xffffffffu, rc.z, off);
                float ow  = __shfl_down_sync(0xffffffffu, rc.w, off);
                if (os > rs || (os == rs && osl < rsl)) {
                    rs = os; rsl = osl;
                    rc.x = ox; rc.y = oy; rc.z = oz; rc.w = ow;
                }
            }
            if (lane == 0) {
                s_bs = rs;
                s_bslot = rsl;
                s_bc = rc;
            }
        }
        __syncthreads();

        float bs = s_bs;
        if (bs < 0.0f) break;       // no active candidates remain (uniform)

        int bslot = s_bslot;
        float4 bc = s_bc;

        if (tid == 0) {
            g_selbox[b][ndet]   = bc;
            g_selscore[b][ndet] = bs;
            g_selidx[b][ndet]   = g_idx[b][bslot];
        }
        ndet++;

        // broadcast winner as next round's suppressor
        bx0 = bc.x; by0 = bc.y; bx1 = bc.z; by1 = bc.w;
        barea = (bx1 - bx0) * (by1 - by0);
        haveBest = true;

        // explicit self-clear of the winner (handles degenerate zero-area box)
        if ((bslot & 1023) == tid) {
            mask &= ~(1u << (bslot >> 10));
        }
        // s_bs is re-written only after the next round's __syncthreads -> safe
    }

    if (tid == 0) g_selcount[b] = ndet;
}

// ---------------------------------------------------------------------------
// Kernel 3: write outputs. One warp per (batch, det). Zeros past count.
// ---------------------------------------------------------------------------
__global__ void __launch_bounds__(256, 4)
write_kernel(const float* __restrict__ class_prob, float* __restrict__ out)
{
    int gw = (blockIdx.x * blockDim.x + threadIdx.x) >> 5;
    int lane = threadIdx.x & 31;

    if (gw < BB * MAXDET) {
        int b = gw / MAXDET;
        int i = gw - b * MAXDET;
        int cntb = g_selcount[b];
        bool valid = (i < cntb);

        float4 box = make_float4(0.f, 0.f, 0.f, 0.f);
        float scv = 0.0f;
        int orig = 0;
        if (valid) {
            box  = g_selbox[b][i];
            scv  = g_selscore[b][i];
            orig = g_selidx[b][i];
        }

        if (lane == 0) {
            float* p = out + OFF_BOX + (size_t)(b * MAXDET + i) * 4;
            p[0] = box.x; p[1] = box.y; p[2] = box.z; p[3] = box.w;
            out[OFF_SCORE + b * MAXDET + i] = scv;
        }
        const float* cp = class_prob + ((size_t)b * NN + orig) * CC;
        float* co = out + OFF_CLS + (size_t)(b * MAXDET + i) * CC;
        #pragma unroll
        for (int c = lane; c < CC; c += 32) {
            co[c] = valid ? cp[c] : 0.0f;
        }
    }

    if (blockIdx.x == 0 && threadIdx.x < BB) {
        out[OFF_CNT + threadIdx.x] = (float)g_selcount[threadIdx.x];
    }
}

// ---------------------------------------------------------------------------
extern "C" void kernel_launch(void* const* d_in, const int* in_sizes, int n_in,
                              void* d_out, int out_size)
{
    const float* boxes = (const float*)d_in[0];   // (16, 25200, 4)
    const float* obj   = (const float*)d_in[1];   // (16, 25200, 1)
    const float* cls   = (const float*)d_in[2];   // (16, 25200, 80)
    float* out = (float*)d_out;

    compact_kernel<<<BB, 1024>>>(boxes, obj);
    nms_kernel<<<BB, 1024>>>();
    // BB*MAXDET warps total -> 1600 warps -> 200 blocks of 256 threads
    write_kernel<<<(BB * MAXDET * 32 + 255) / 256, 256>>>(cls, out);
}